// round 1
// baseline (speedup 1.0000x reference)
#include <cuda_runtime.h>
#include <cstdint>

// Problem constants
#define BS   32
#define CLS  80
#define HH   128
#define WW   128
#define HW   16384
#define K    100
#define CAND_CAP  4096   // max possible strict peaks in 128x128 (checkerboard)
#define FINAL_CAP 256

// Output layout (fp32, concatenated in reference return order)
#define OFF_SC   0                      // (32,80,100) per-class topk scores
#define OFF_IND  (BS*CLS*K)             // 256000
#define OFF_CLSO (OFF_IND + BS*K)       // 259200
#define OFF_YS   (OFF_CLSO + BS*K)      // 262400
#define OFF_XS   (OFF_YS + BS*K)        // 265600

// Scratch: per-class top-100 flat spatial indices
__device__ int g_idx1[BS * CLS * K];

__device__ __forceinline__ float fmax3f(float a, float b, float c) {
    return fmaxf(a, fmaxf(b, c));
}

__device__ __forceinline__ unsigned long long make_key(unsigned score_bits, unsigned idx) {
    // max-order == (score desc, idx asc); scores >= 0 so bit pattern is monotone
    return ((unsigned long long)score_bits << 32) | (unsigned)(~idx);
}

// Block-wide sum reduction (256 threads). Two barriers; s_red has 8 slots.
__device__ __forceinline__ int block_sum_256(int v, int* s_red, int tid) {
    #pragma unroll
    for (int o = 16; o > 0; o >>= 1) v += __shfl_down_sync(0xFFFFFFFFu, v, o);
    if ((tid & 31) == 0) s_red[tid >> 5] = v;
    __syncthreads();
    int tot = s_red[0] + s_red[1] + s_red[2] + s_red[3]
            + s_red[4] + s_red[5] + s_red[6] + s_red[7];
    __syncthreads();   // s_red reused next iteration
    return tot;
}

// Descending bitonic sort of FINAL_CAP=256 u64 keys, 256 threads.
__device__ __forceinline__ void bitonic_sort_256(unsigned long long* s_final, int tid) {
    #pragma unroll
    for (int k2 = 2; k2 <= FINAL_CAP; k2 <<= 1) {
        for (int j = k2 >> 1; j > 0; j >>= 1) {
            int ixj = tid ^ j;
            if (ixj > tid) {
                bool desc = ((tid & k2) == 0);
                unsigned long long x = s_final[tid], y = s_final[ixj];
                bool sw = desc ? (x < y) : (x > y);
                if (sw) { s_final[tid] = y; s_final[ixj] = x; }
            }
            __syncthreads();
        }
    }
}

// ---------------------------------------------------------------------------
// Stage 1: one CTA per (b,c). NMS + exact per-class top-100 (score desc, idx asc)
// ---------------------------------------------------------------------------
__global__ void __launch_bounds__(256, 4)
stage1_kernel(const float* __restrict__ hm, float* __restrict__ out)
{
    __shared__ unsigned long long s_cand[CAND_CAP];
    __shared__ unsigned long long s_final[FINAL_CAP];
    __shared__ int s_red[8];
    __shared__ int s_ncand, s_nfinal;

    const int bc  = blockIdx.x;            // 0..2559
    const int tid = threadIdx.x;
    const int lane = tid & 31;
    const float* __restrict__ t = hm + (size_t)bc * HW;

    if (tid == 0) { s_ncand = 0; s_nfinal = 0; }
    __syncthreads();

    // --- NMS over 4-cell groups, compact peaks into s_cand ------------------
    const float NEG = -3.0e38f;
    #pragma unroll 1
    for (int g = 0; g < 16; ++g) {
        int gi = g * 256 + tid;            // 0..4095 groups of 4 cells
        int r  = gi >> 5;                  // 32 groups per row
        int c0 = (gi & 31) << 2;

        float v0 = NEG, v1 = NEG, v2 = NEG, v3 = NEG, v4 = NEG, v5 = NEG;
        float a0 = 0.f, a1 = 0.f, a2 = 0.f, a3 = 0.f;
        #pragma unroll
        for (int dr = -1; dr <= 1; ++dr) {
            int rr = r + dr;
            if (rr < 0 || rr > HH - 1) continue;
            const float* row = t + rr * WW + c0;
            float4 m = *(const float4*)row;
            float lft = (c0 > 0)        ? row[-1] : NEG;
            float rgt = (c0 < WW - 4)   ? row[4]  : NEG;
            v0 = fmaxf(v0, lft);
            v1 = fmaxf(v1, m.x); v2 = fmaxf(v2, m.y);
            v3 = fmaxf(v3, m.z); v4 = fmaxf(v4, m.w);
            v5 = fmaxf(v5, rgt);
            if (dr == 0) { a0 = m.x; a1 = m.y; a2 = m.z; a3 = m.w; }
        }

        unsigned long long loc[4];
        int n = 0;
        int base_idx = r * WW + c0;
        if (fmax3f(v0, v1, v2) == a0) loc[n++] = make_key(__float_as_uint(a0), base_idx + 0);
        if (fmax3f(v1, v2, v3) == a1) loc[n++] = make_key(__float_as_uint(a1), base_idx + 1);
        if (fmax3f(v2, v3, v4) == a2) loc[n++] = make_key(__float_as_uint(a2), base_idx + 2);
        if (fmax3f(v3, v4, v5) == a3) loc[n++] = make_key(__float_as_uint(a3), base_idx + 3);

        // warp-aggregated append
        int incl = n;
        #pragma unroll
        for (int o = 1; o < 32; o <<= 1) {
            int x = __shfl_up_sync(0xFFFFFFFFu, incl, o);
            if (lane >= o) incl += x;
        }
        int total = __shfl_sync(0xFFFFFFFFu, incl, 31);
        int wbase = 0;
        if (lane == 31 && total > 0) wbase = atomicAdd(&s_ncand, total);
        wbase = __shfl_sync(0xFFFFFFFFu, wbase, 31);
        int off0 = wbase + incl - n;
        for (int j = 0; j < n; ++j) {
            int p = off0 + j;
            if (p < CAND_CAP) s_cand[p] = loc[j];
        }
    }
    __syncthreads();
    int ncand = min(s_ncand, CAND_CAP);

    // --- Pathological fallback: <100 peaks -> append zero-valued non-peaks --
    if (ncand < K) {
        int idx = tid;                     // first 256 cells contain the 100
        int r = idx >> 7, c = idx & (WW - 1);   // smallest-index non-peaks
        float v = t[idx];
        float m = v;
        for (int dr = -1; dr <= 1; ++dr)
            for (int dc = -1; dc <= 1; ++dc) {
                int rr = r + dr, cc = c + dc;
                if (rr >= 0 && rr < HH && cc >= 0 && cc < WW)
                    m = fmaxf(m, t[rr * WW + cc]);
            }
        if (m != v) {   // suppressed cell: value 0 after keep-mask
            int p = atomicAdd(&s_ncand, 1);
            if (p < CAND_CAP) s_cand[p] = make_key(0u, idx);
        }
        __syncthreads();
        ncand = min(s_ncand, CAND_CAP);
    }

    // --- Register-resident keys for the bisect ------------------------------
    unsigned long long kreg[16];
    #pragma unroll
    for (int j = 0; j < 16; ++j) {
        int i = tid + j * 256;
        kreg[j] = (i < ncand) ? s_cand[i] : 0ULL;
    }

    // --- Binary search for the exact 100th-largest score bit pattern --------
    unsigned lo = 0u, hi = 0x40000000u;    // scores in [0,1): f(lo)>=K, f(hi)=0
    while (hi - lo > 1u) {
        unsigned mid = (lo + hi) >> 1;
        int cnt = 0;
        #pragma unroll
        for (int j = 0; j < 16; ++j)
            cnt += ((unsigned)(kreg[j] >> 32) >= mid) ? 1 : 0;
        int tot = block_sum_256(cnt, s_red, tid);
        if (tot >= K) lo = mid; else hi = mid;
    }
    const unsigned T = lo;

    // --- Collect candidates >= T, pad, sort, emit ---------------------------
    #pragma unroll
    for (int j = 0; j < 16; ++j) {
        int i = tid + j * 256;
        if (i < ncand) {
            unsigned long long kk = kreg[j];
            if ((unsigned)(kk >> 32) >= T) {
                int p = atomicAdd(&s_nfinal, 1);
                if (p < FINAL_CAP) s_final[p] = kk;
            }
        }
    }
    __syncthreads();
    int nf = min(s_nfinal, FINAL_CAP);
    if (tid >= nf) s_final[tid] = 0ULL;
    __syncthreads();

    bitonic_sort_256(s_final, tid);

    if (tid < K) {
        unsigned long long kk = s_final[tid];
        float sc = __uint_as_float((unsigned)(kk >> 32));
        int flat = (int)(~(unsigned)kk);          // recover flat index exactly
        out[OFF_SC + bc * K + tid] = sc;
        g_idx1[bc * K + tid] = flat;
    }
}

// ---------------------------------------------------------------------------
// Stage 2: one CTA per batch. Global top-100 over C*K=8000 per-class scores.
// ---------------------------------------------------------------------------
__global__ void __launch_bounds__(256)
stage2_kernel(const float* __restrict__ out_scores, float* __restrict__ out)
{
    __shared__ unsigned long long s_final[FINAL_CAP];
    __shared__ int s_red[8];
    __shared__ int s_nfinal;

    const int b   = blockIdx.x;            // 0..31
    const int tid = threadIdx.x;
    const int NC  = CLS * K;               // 8000
    const float* __restrict__ sc = out_scores + OFF_SC + (size_t)b * NC;

    if (tid == 0) s_nfinal = 0;
    __syncthreads();

    unsigned long long kreg[32];
    #pragma unroll
    for (int j = 0; j < 32; ++j) {
        int i = tid + j * 256;
        kreg[j] = (i < NC) ? make_key(__float_as_uint(sc[i]), (unsigned)i) : 0ULL;
    }

    unsigned lo = 0u, hi = 0x40000000u;
    while (hi - lo > 1u) {
        unsigned mid = (lo + hi) >> 1;
        int cnt = 0;
        #pragma unroll
        for (int j = 0; j < 32; ++j)
            cnt += ((unsigned)(kreg[j] >> 32) >= mid) ? 1 : 0;
        int tot = block_sum_256(cnt, s_red, tid);
        if (tot >= K) lo = mid; else hi = mid;
    }
    const unsigned T = lo;

    #pragma unroll
    for (int j = 0; j < 32; ++j) {
        int i = tid + j * 256;
        if (i < NC) {
            unsigned long long kk = kreg[j];
            if ((unsigned)(kk >> 32) >= T) {
                int p = atomicAdd(&s_nfinal, 1);
                if (p < FINAL_CAP) s_final[p] = kk;
            }
        }
    }
    __syncthreads();
    int nf = min(s_nfinal, FINAL_CAP);
    if (tid >= nf) s_final[tid] = 0ULL;
    __syncthreads();

    bitonic_sort_256(s_final, tid);

    if (tid < K) {
        unsigned long long kk = s_final[tid];
        int ci     = (int)(~(unsigned)kk);          // combined index in [0,8000)
        int classe = ci / K;
        int flat   = g_idx1[b * NC + ci];
        out[OFF_IND  + b * K + tid] = (float)flat;
        out[OFF_CLSO + b * K + tid] = (float)classe;
        out[OFF_YS   + b * K + tid] = (float)(flat >> 7);   // y = flat / 128
        out[OFF_XS   + b * K + tid] = (float)(flat & 127);  // x = flat % 128
    }
}

// ---------------------------------------------------------------------------
extern "C" void kernel_launch(void* const* d_in, const int* in_sizes, int n_in,
                              void* d_out, int out_size)
{
    const float* hm = (const float*)d_in[0];
    float* out = (float*)d_out;
    stage1_kernel<<<BS * CLS, 256>>>(hm, out);
    stage2_kernel<<<BS, 256>>>(out, out);
}

// round 4
// speedup vs baseline: 1.5760x; 1.5760x over previous
#include <cuda_runtime.h>
#include <cstdint>

// Problem constants
#define BS   32
#define CLS  80
#define HH   128
#define WW   128
#define HW   16384
#define K    100
#define CAND_CAP  4096   // max strict peaks in 128x128 (independent set)
#define FINAL_CAP 256

// Output layout (fp32, concatenated in reference return order)
#define OFF_SC   0                      // (32,80,100) per-class topk scores
#define OFF_IND  (BS*CLS*K)             // 256000
#define OFF_CLSO (OFF_IND + BS*K)       // 259200
#define OFF_YS   (OFF_CLSO + BS*K)      // 262400
#define OFF_XS   (OFF_YS + BS*K)        // 265600

// Scratch: per-class top-100 flat spatial indices
__device__ int g_idx1[BS * CLS * K];

__device__ __forceinline__ unsigned long long make_key(unsigned sb, unsigned idx) {
    // max-order == (score desc, idx asc); scores >= 0 so bit pattern is monotone
    return ((unsigned long long)sb << 32) | (unsigned)(~idx);
}

__device__ __forceinline__ int block_sum_256(int v, int* s_red, int tid) {
    #pragma unroll
    for (int o = 16; o > 0; o >>= 1) v += __shfl_down_sync(0xFFFFFFFFu, v, o);
    if ((tid & 31) == 0) s_red[tid >> 5] = v;
    __syncthreads();
    int tot = s_red[0] + s_red[1] + s_red[2] + s_red[3]
            + s_red[4] + s_red[5] + s_red[6] + s_red[7];
    __syncthreads();
    return tot;
}

__device__ __forceinline__ unsigned long long
block_max_256(unsigned long long v, unsigned long long* s_tmp, int tid) {
    #pragma unroll
    for (int o = 16; o > 0; o >>= 1) {
        unsigned long long x = __shfl_down_sync(0xFFFFFFFFu, v, o);
        v = (v > x) ? v : x;
    }
    if ((tid & 31) == 0) s_tmp[tid >> 5] = v;
    __syncthreads();
    unsigned long long m = s_tmp[0];
    #pragma unroll
    for (int i = 1; i < 8; ++i) { unsigned long long x = s_tmp[i]; m = (m > x) ? m : x; }
    __syncthreads();
    return m;
}

// Descending bitonic sort of 256 u64 keys, 256 threads.
__device__ __forceinline__ void bitonic_sort_256(unsigned long long* s_final, int tid) {
    #pragma unroll
    for (int k2 = 2; k2 <= FINAL_CAP; k2 <<= 1) {
        for (int j = k2 >> 1; j > 0; j >>= 1) {
            int ixj = tid ^ j;
            if (ixj > tid) {
                bool desc = ((tid & k2) == 0);
                unsigned long long x = s_final[tid], y = s_final[ixj];
                bool sw = desc ? (x < y) : (x > y);
                if (sw) { s_final[tid] = y; s_final[ixj] = x; }
            }
            __syncthreads();
        }
    }
}

__device__ __forceinline__ void load6(const float* __restrict__ t, int r, int c0, float v[6]) {
    const float NEG = -3.0e38f;
    if (r < 0 || r >= HH) {
        #pragma unroll
        for (int j = 0; j < 6; ++j) v[j] = NEG;
        return;
    }
    const float* row = t + r * WW + c0;
    float4 m = *(const float4*)row;
    v[0] = (c0 > 0)      ? __ldg(row - 1) : NEG;
    v[1] = m.x; v[2] = m.y; v[3] = m.z; v[4] = m.w;
    v[5] = (c0 < WW - 4) ? __ldg(row + 4) : NEG;
}

// ---------------------------------------------------------------------------
// Stage 1: one CTA per (b,c). Rolling-register NMS + shared-memory bisect
// top-100 (exact JAX order: score desc, flat idx asc).
// ---------------------------------------------------------------------------
__global__ void __launch_bounds__(256, 4)
stage1_kernel(const float* __restrict__ hm, float* __restrict__ out)
{
    __shared__ unsigned long long s_cand[CAND_CAP];
    __shared__ unsigned long long s_final[FINAL_CAP];
    __shared__ unsigned long long s_tmp64[8];
    __shared__ int s_red[8];
    __shared__ int s_ncand, s_nfinal;

    const int bc   = blockIdx.x;           // 0..2559
    const int tid  = threadIdx.x;
    const int lane = tid & 31;
    const float* __restrict__ t = hm + (size_t)bc * HW;

    if (tid == 0) { s_ncand = 0; s_nfinal = 0; }
    __syncthreads();

    // --- NMS: thread owns 4-col strip (c0) x 16 rows (r0..r0+15) ------------
    const int c0 = (tid & 31) << 2;        // 0,4,...,124
    const int r0 = (tid >> 5) << 4;        // warp w owns rows [16w,16w+16)

    float A[6], Bv[6], Cv[6];
    load6(t, r0 - 1, c0, A);
    load6(t, r0,     c0, Bv);

    const unsigned lt = (1u << lane) - 1u;

    #pragma unroll
    for (int rr = 0; rr < 16; ++rr) {
        const int r = r0 + rr;
        load6(t, r + 1, c0, Cv);

        float vm0 = fmaxf(fmaxf(A[0], Bv[0]), Cv[0]);
        float vm1 = fmaxf(fmaxf(A[1], Bv[1]), Cv[1]);
        float vm2 = fmaxf(fmaxf(A[2], Bv[2]), Cv[2]);
        float vm3 = fmaxf(fmaxf(A[3], Bv[3]), Cv[3]);
        float vm4 = fmaxf(fmaxf(A[4], Bv[4]), Cv[4]);
        float vm5 = fmaxf(fmaxf(A[5], Bv[5]), Cv[5]);

        float t01 = fmaxf(vm0, vm1), t12 = fmaxf(vm1, vm2), t23 = fmaxf(vm2, vm3);
        float t34 = fmaxf(vm3, vm4), t45 = fmaxf(vm4, vm5);
        bool p1 = (fmaxf(t01, vm2) == Bv[1]);
        bool p2 = (fmaxf(t12, vm3) == Bv[2]);
        bool p3 = (fmaxf(t23, vm4) == Bv[3]);
        bool p4 = (fmaxf(t34, t45) == Bv[4]);

        unsigned m1 = __ballot_sync(0xFFFFFFFFu, p1);
        unsigned m2 = __ballot_sync(0xFFFFFFFFu, p2);
        unsigned m3 = __ballot_sync(0xFFFFFFFFu, p3);
        unsigned m4 = __ballot_sync(0xFFFFFFFFu, p4);
        int tot = __popc(m1) + __popc(m2) + __popc(m3) + __popc(m4);
        if (tot) {
            int base = 0;
            if (lane == 0) base = atomicAdd(&s_ncand, tot);
            base = __shfl_sync(0xFFFFFFFFu, base, 0);
            const int bidx = r * WW + c0;
            int o = base, p;
            if (p1) { p = o + __popc(m1 & lt); if (p < CAND_CAP) s_cand[p] = make_key(__float_as_uint(Bv[1]), bidx + 0); }
            o += __popc(m1);
            if (p2) { p = o + __popc(m2 & lt); if (p < CAND_CAP) s_cand[p] = make_key(__float_as_uint(Bv[2]), bidx + 1); }
            o += __popc(m2);
            if (p3) { p = o + __popc(m3 & lt); if (p < CAND_CAP) s_cand[p] = make_key(__float_as_uint(Bv[3]), bidx + 2); }
            o += __popc(m3);
            if (p4) { p = o + __popc(m4 & lt); if (p < CAND_CAP) s_cand[p] = make_key(__float_as_uint(Bv[4]), bidx + 3); }
        }

        #pragma unroll
        for (int j = 0; j < 6; ++j) { A[j] = Bv[j]; Bv[j] = Cv[j]; }
    }
    __syncthreads();
    int ncand = min(s_ncand, CAND_CAP);

    // --- Pathological fallback: <100 peaks -> append zero-score non-peaks ---
    if (ncand < K) {
        int idx = tid;                     // first 256 cells contain the 100
        int r = idx >> 7, c = idx & (WW - 1);  // smallest-index suppressed cells
        float v = t[idx];
        float m = v;
        for (int dr = -1; dr <= 1; ++dr)
            for (int dc = -1; dc <= 1; ++dc) {
                int rr2 = r + dr, cc = c + dc;
                if (rr2 >= 0 && rr2 < HH && cc >= 0 && cc < WW)
                    m = fmaxf(m, t[rr2 * WW + cc]);
            }
        if (m != v) {   // suppressed: value 0 after keep-mask
            int p = atomicAdd(&s_ncand, 1);
            if (p < CAND_CAP) s_cand[p] = make_key(0u, idx);
        }
        __syncthreads();
        ncand = min(s_ncand, CAND_CAP);
    }

    // --- Tight bisect range: block max key --------------------------------
    unsigned long long mx = 0ULL;
    for (int i = tid; i < ncand; i += 256) {
        unsigned long long kk = s_cand[i];
        mx = (kk > mx) ? kk : mx;
    }
    mx = block_max_256(mx, s_tmp64, tid);

    // --- Early-exit bisect on u64 key over shared candidates --------------
    unsigned long long lo = 0ULL, hi = mx + 1ULL;
    while (hi - lo > 1ULL) {
        unsigned long long mid = lo + ((hi - lo) >> 1);
        int c = 0;
        for (int i = tid; i < ncand; i += 256) c += (s_cand[i] >= mid) ? 1 : 0;
        int tot = block_sum_256(c, s_red, tid);
        if (tot >= K) { lo = mid; if (tot <= FINAL_CAP) break; }
        else hi = mid;
    }
    const unsigned long long T = lo;   // count(>=T) in [K, FINAL_CAP]

    // --- Collect survivors, pad, sort, emit --------------------------------
    for (int i = tid; i < ncand; i += 256) {
        unsigned long long kk = s_cand[i];
        if (kk >= T) {
            int p = atomicAdd(&s_nfinal, 1);
            if (p < FINAL_CAP) s_final[p] = kk;
        }
    }
    __syncthreads();
    int nf = min(s_nfinal, FINAL_CAP);
    if (tid >= nf) s_final[tid] = 0ULL;
    __syncthreads();

    bitonic_sort_256(s_final, tid);

    if (tid < K) {
        unsigned long long kk = s_final[tid];
        out[OFF_SC + bc * K + tid] = __uint_as_float((unsigned)(kk >> 32));
        g_idx1[bc * K + tid] = (int)(~(unsigned)kk);
    }
}

// ---------------------------------------------------------------------------
// Stage 2: one CTA per batch. Global top-100 over C*K=8000 per-class scores.
// Scores cached in shared as u32; keys rebuilt on the fly (idx == position).
// ---------------------------------------------------------------------------
__global__ void __launch_bounds__(256)
stage2_kernel(const float* __restrict__ out_scores, float* __restrict__ out)
{
    __shared__ unsigned s_sc[CLS * K];               // 8000 * 4B
    __shared__ unsigned long long s_final[FINAL_CAP];
    __shared__ unsigned long long s_tmp64[8];
    __shared__ int s_red[8];
    __shared__ int s_nfinal;

    const int b   = blockIdx.x;
    const int tid = threadIdx.x;
    const int NC  = CLS * K;
    const float* __restrict__ sc = out_scores + OFF_SC + (size_t)b * NC;

    if (tid == 0) s_nfinal = 0;
    for (int i = tid; i < NC; i += 256) s_sc[i] = __float_as_uint(sc[i]);
    __syncthreads();

    unsigned long long mx = 0ULL;
    for (int i = tid; i < NC; i += 256) {
        unsigned long long kk = make_key(s_sc[i], (unsigned)i);
        mx = (kk > mx) ? kk : mx;
    }
    mx = block_max_256(mx, s_tmp64, tid);

    unsigned long long lo = 0ULL, hi = mx + 1ULL;
    while (hi - lo > 1ULL) {
        unsigned long long mid = lo + ((hi - lo) >> 1);
        int c = 0;
        for (int i = tid; i < NC; i += 256)
            c += (make_key(s_sc[i], (unsigned)i) >= mid) ? 1 : 0;
        int tot = block_sum_256(c, s_red, tid);
        if (tot >= K) { lo = mid; if (tot <= FINAL_CAP) break; }
        else hi = mid;
    }
    const unsigned long long T = lo;

    for (int i = tid; i < NC; i += 256) {
        unsigned long long kk = make_key(s_sc[i], (unsigned)i);
        if (kk >= T) {
            int p = atomicAdd(&s_nfinal, 1);
            if (p < FINAL_CAP) s_final[p] = kk;
        }
    }
    __syncthreads();
    int nf = min(s_nfinal, FINAL_CAP);
    if (tid >= nf) s_final[tid] = 0ULL;
    __syncthreads();

    bitonic_sort_256(s_final, tid);

    if (tid < K) {
        unsigned long long kk = s_final[tid];
        int ci     = (int)(~(unsigned)kk);          // combined index in [0,8000)
        int classe = ci / K;
        int flat   = g_idx1[b * NC + ci];
        out[OFF_IND  + b * K + tid] = (float)flat;
        out[OFF_CLSO + b * K + tid] = (float)classe;
        out[OFF_YS   + b * K + tid] = (float)(flat >> 7);   // y = flat / 128
        out[OFF_XS   + b * K + tid] = (float)(flat & 127);  // x = flat % 128
    }
}

// ---------------------------------------------------------------------------
extern "C" void kernel_launch(void* const* d_in, const int* in_sizes, int n_in,
                              void* d_out, int out_size)
{
    const float* hm = (const float*)d_in[0];
    float* out = (float*)d_out;
    stage1_kernel<<<BS * CLS, 256>>>(hm, out);
    stage2_kernel<<<BS, 256>>>(out, out);
}

// round 5
// speedup vs baseline: 2.0812x; 1.3206x over previous
#include <cuda_runtime.h>
#include <cstdint>

// Problem constants
#define BS   32
#define CLS  80
#define HH   128
#define WW   128
#define HW   16384
#define K    100
#define CAND_CAP  3072   // ~35 sigma above expected ~1850 peaks
#define FINAL_CAP 256

// Output layout (fp32, concatenated in reference return order)
#define OFF_SC   0                      // (32,80,100) per-class topk scores
#define OFF_IND  (BS*CLS*K)             // 256000
#define OFF_CLSO (OFF_IND + BS*K)       // 259200
#define OFF_YS   (OFF_CLSO + BS*K)      // 262400
#define OFF_XS   (OFF_YS + BS*K)        // 265600

// Scratch: per-class top-100 flat spatial indices
__device__ int g_idx1[BS * CLS * K];

__device__ __forceinline__ unsigned long long make_key(unsigned sb, unsigned idx) {
    // max-order == (score desc, idx asc); scores >= 0 so bit pattern is monotone
    return ((unsigned long long)sb << 32) | (unsigned)(~idx);
}

// Inclusive suffix-scan over 256 histogram bins.
// After call: s_scan[p] = sum of s_hist[255-p .. 255]  (suffix(d) = s_scan[255-d]).
__device__ __forceinline__ void suffix_scan_store(const int* s_hist, int* s_scan,
                                                  int* s_red, int tid, int lane, int warp) {
    int incl = s_hist[255 - tid];
    #pragma unroll
    for (int o = 1; o < 32; o <<= 1) {
        int x = __shfl_up_sync(0xFFFFFFFFu, incl, o);
        if (lane >= o) incl += x;
    }
    if (lane == 31) s_red[warp] = incl;
    __syncthreads();
    int off = 0;
    #pragma unroll
    for (int w = 0; w < 8; ++w) off += (w < warp) ? s_red[w] : 0;
    s_scan[tid] = incl + off;
    __syncthreads();
}

// Load 10 floats (cols c0-1 .. c0+8) of row r, NEG-filled out of bounds.
__device__ __forceinline__ void load10(const float* __restrict__ t, int r, int c0,
                                       bool hasL, bool hasR, float v[10]) {
    const float NEG = -3.0e38f;
    if ((unsigned)r >= (unsigned)HH) {
        #pragma unroll
        for (int j = 0; j < 10; ++j) v[j] = NEG;
        return;
    }
    const float* row = t + r * WW + c0;
    float4 a = *(const float4*)row;
    float4 b = *(const float4*)(row + 4);
    v[0] = hasL ? __ldg(row - 1) : NEG;
    v[1] = a.x; v[2] = a.y; v[3] = a.z; v[4] = a.w;
    v[5] = b.x; v[6] = b.y; v[7] = b.z; v[8] = b.w;
    v[9] = hasR ? __ldg(row + 8) : NEG;
}

// ---------------------------------------------------------------------------
// Stage 1: one CTA per (b,c). 8x8 strip rolling NMS + radix-select top-100.
// Exact JAX order: score desc, flat idx asc.
// ---------------------------------------------------------------------------
__global__ void __launch_bounds__(256, 4)
stage1_kernel(const float* __restrict__ hm, float* __restrict__ out)
{
    __shared__ unsigned long long s_cand[CAND_CAP];
    __shared__ unsigned long long s_final[FINAL_CAP];
    __shared__ int s_hist[256];
    __shared__ int s_scan[256];
    __shared__ int s_red[8];
    __shared__ int s_sel;
    __shared__ int s_ncand, s_nfinal;

    const int bc   = blockIdx.x;           // 0..2559
    const int tid  = threadIdx.x;
    const int lane = tid & 31;
    const int warp = tid >> 5;
    const float* __restrict__ t = hm + (size_t)bc * HW;

    if (tid == 0) { s_ncand = 0; s_nfinal = 0; }
    __syncthreads();

    // --- NMS: thread owns 8-col strip x 8 rows -----------------------------
    const int c0 = (tid & 15) << 3;        // 0,8,...,120
    const int r0 = (tid >> 4) << 3;        // 16 bands of 8 rows
    const bool hasL = (c0 > 0);
    const bool hasR = (c0 < WW - 8);

    float Bv[10], pm[10], Cv[10];
    load10(t, r0 - 1, c0, hasL, hasR, pm);     // row above (as A)
    load10(t, r0,     c0, hasL, hasR, Bv);     // center row
    #pragma unroll
    for (int j = 0; j < 10; ++j) pm[j] = fmaxf(pm[j], Bv[j]);   // pm = max(A,B)

    #pragma unroll
    for (int rr = 0; rr < 8; ++rr) {
        const int r = r0 + rr;
        load10(t, r + 1, c0, hasL, hasR, Cv);

        float vm[10];
        #pragma unroll
        for (int j = 0; j < 10; ++j) vm[j] = fmaxf(pm[j], Cv[j]);  // 3-row col max
        float tj[9];
        #pragma unroll
        for (int j = 0; j < 9; ++j) tj[j] = fmaxf(vm[j], vm[j + 1]);

        unsigned mask = 0;
        #pragma unroll
        for (int j = 0; j < 8; ++j)
            mask |= (fmaxf(tj[j], vm[j + 2]) == Bv[j + 1]) ? (1u << j) : 0u;

        int n = __popc(mask);
        int incl = n;
        #pragma unroll
        for (int o = 1; o < 32; o <<= 1) {
            int x = __shfl_up_sync(0xFFFFFFFFu, incl, o);
            if (lane >= o) incl += x;
        }
        int wtot = __shfl_sync(0xFFFFFFFFu, incl, 31);
        if (wtot) {
            int base = 0;
            if (lane == 31) base = atomicAdd(&s_ncand, wtot);
            base = __shfl_sync(0xFFFFFFFFu, base, 31);
            int pos = base + incl - n;
            const int cb = r * WW + c0;
            if (mask & 1u)   { if (pos < CAND_CAP) s_cand[pos] = make_key(__float_as_uint(Bv[1]), cb + 0); pos++; }
            if (mask & 2u)   { if (pos < CAND_CAP) s_cand[pos] = make_key(__float_as_uint(Bv[2]), cb + 1); pos++; }
            if (mask & 4u)   { if (pos < CAND_CAP) s_cand[pos] = make_key(__float_as_uint(Bv[3]), cb + 2); pos++; }
            if (mask & 8u)   { if (pos < CAND_CAP) s_cand[pos] = make_key(__float_as_uint(Bv[4]), cb + 3); pos++; }
            if (mask & 16u)  { if (pos < CAND_CAP) s_cand[pos] = make_key(__float_as_uint(Bv[5]), cb + 4); pos++; }
            if (mask & 32u)  { if (pos < CAND_CAP) s_cand[pos] = make_key(__float_as_uint(Bv[6]), cb + 5); pos++; }
            if (mask & 64u)  { if (pos < CAND_CAP) s_cand[pos] = make_key(__float_as_uint(Bv[7]), cb + 6); pos++; }
            if (mask & 128u) { if (pos < CAND_CAP) s_cand[pos] = make_key(__float_as_uint(Bv[8]), cb + 7); pos++; }
        }

        #pragma unroll
        for (int j = 0; j < 10; ++j) { pm[j] = fmaxf(Bv[j], Cv[j]); Bv[j] = Cv[j]; }
    }
    __syncthreads();
    int ncand = min(s_ncand, CAND_CAP);

    // --- Pathological fallback: <100 peaks -> append zero-score non-peaks ---
    if (ncand < K) {
        int idx = tid;                     // first 256 cells contain the 100
        int r = idx >> 7, c = idx & (WW - 1);
        float v = t[idx];
        float m = v;
        for (int dr = -1; dr <= 1; ++dr)
            for (int dc = -1; dc <= 1; ++dc) {
                int rr2 = r + dr, cc = c + dc;
                if (rr2 >= 0 && rr2 < HH && cc >= 0 && cc < WW)
                    m = fmaxf(m, t[rr2 * WW + cc]);
            }
        if (m != v) {   // suppressed: value 0 after keep-mask
            int p = atomicAdd(&s_ncand, 1);
            if (p < CAND_CAP) s_cand[p] = make_key(0u, idx);
        }
        __syncthreads();
        ncand = min(s_ncand, CAND_CAP);
    }

    // --- Radix-select: find floor Tf with count(>=Tf) in [K, FINAL_CAP] -----
    int need = K;
    int total_above = 0;
    unsigned long long prefix = 0;
    unsigned long long Tf = 0;
    for (int shift = 56;; shift -= 8) {
        s_hist[tid] = 0;
        __syncthreads();
        for (int i = tid; i < ncand; i += 256) {
            unsigned long long kk = s_cand[i];
            unsigned long long sh = kk >> shift;
            if ((sh >> 8) == prefix) atomicAdd(&s_hist[(int)(sh & 255u)], 1);
        }
        __syncthreads();
        suffix_scan_store(s_hist, s_scan, s_red, tid, lane, warp);
        {
            int d = tid;
            int suf  = s_scan[255 - d];
            int suf1 = (d == 255) ? 0 : s_scan[254 - d];
            if (suf >= need && suf1 < need) s_sel = d;
        }
        __syncthreads();
        int dsel  = s_sel;
        int A     = (dsel == 255) ? 0 : s_scan[254 - dsel];
        int inbin = s_scan[255 - dsel] - A;
        prefix = (prefix << 8) | (unsigned)dsel;
        total_above += A;
        need -= A;
        if (total_above + inbin <= FINAL_CAP || shift == 0) {
            Tf = prefix << shift;
            break;
        }
        __syncthreads();   // protect s_sel/s_scan before next round overwrites
    }
    __syncthreads();

    // --- Collect survivors (<=256) and rank-emit ---------------------------
    for (int i = tid; i < ncand; i += 256) {
        unsigned long long kk = s_cand[i];
        if (kk >= Tf) {
            int p = atomicAdd(&s_nfinal, 1);
            if (p < FINAL_CAP) s_final[p] = kk;
        }
    }
    __syncthreads();
    int nf = min(s_nfinal, FINAL_CAP);

    if (tid < nf) {
        unsigned long long my = s_final[tid];
        int rank = 0;
        for (int i = 0; i < nf; ++i) rank += (s_final[i] > my) ? 1 : 0;
        if (rank < K) {
            out[OFF_SC + bc * K + rank] = __uint_as_float((unsigned)(my >> 32));
            g_idx1[bc * K + rank] = (int)(~(unsigned)my);
        }
    }
}

// ---------------------------------------------------------------------------
// Stage 2: one CTA per batch. Global top-100 over C*K=8000 per-class scores
// via the same radix-select. 48-bit keys: (score<<16) | (0xFFFF & ~i).
// ---------------------------------------------------------------------------
__device__ __forceinline__ unsigned long long key2(unsigned sb, int i) {
    return ((unsigned long long)sb << 16) | (unsigned)(0xFFFFu & ~(unsigned)i);
}

__global__ void __launch_bounds__(256)
stage2_kernel(const float* __restrict__ out_scores, float* __restrict__ out)
{
    __shared__ unsigned s_sc[CLS * K];               // 8000 * 4B
    __shared__ unsigned long long s_final[FINAL_CAP];
    __shared__ int s_hist[256];
    __shared__ int s_scan[256];
    __shared__ int s_red[8];
    __shared__ int s_sel;
    __shared__ int s_nfinal;

    const int b    = blockIdx.x;
    const int tid  = threadIdx.x;
    const int lane = tid & 31;
    const int warp = tid >> 5;
    const int NC   = CLS * K;
    const float* __restrict__ sc = out_scores + OFF_SC + (size_t)b * NC;

    if (tid == 0) s_nfinal = 0;
    for (int i = tid; i < NC; i += 256) s_sc[i] = __float_as_uint(sc[i]);
    __syncthreads();

    int need = K;
    int total_above = 0;
    unsigned long long prefix = 0;
    unsigned long long Tf = 0;
    for (int shift = 40;; shift -= 8) {
        s_hist[tid] = 0;
        __syncthreads();
        for (int i = tid; i < NC; i += 256) {
            unsigned long long kk = key2(s_sc[i], i);
            unsigned long long sh = kk >> shift;
            if ((sh >> 8) == prefix) atomicAdd(&s_hist[(int)(sh & 255u)], 1);
        }
        __syncthreads();
        suffix_scan_store(s_hist, s_scan, s_red, tid, lane, warp);
        {
            int d = tid;
            int suf  = s_scan[255 - d];
            int suf1 = (d == 255) ? 0 : s_scan[254 - d];
            if (suf >= need && suf1 < need) s_sel = d;
        }
        __syncthreads();
        int dsel  = s_sel;
        int A     = (dsel == 255) ? 0 : s_scan[254 - dsel];
        int inbin = s_scan[255 - dsel] - A;
        prefix = (prefix << 8) | (unsigned)dsel;
        total_above += A;
        need -= A;
        if (total_above + inbin <= FINAL_CAP || shift == 0) {
            Tf = prefix << shift;
            break;
        }
        __syncthreads();
    }
    __syncthreads();

    for (int i = tid; i < NC; i += 256) {
        unsigned long long kk = key2(s_sc[i], i);
        if (kk >= Tf) {
            int p = atomicAdd(&s_nfinal, 1);
            if (p < FINAL_CAP) s_final[p] = kk;
        }
    }
    __syncthreads();
    int nf = min(s_nfinal, FINAL_CAP);

    if (tid < nf) {
        unsigned long long my = s_final[tid];
        int rank = 0;
        for (int i = 0; i < nf; ++i) rank += (s_final[i] > my) ? 1 : 0;
        if (rank < K) {
            int ci     = (int)((~(unsigned)my) & 0xFFFFu);   // combined idx [0,8000)
            int classe = ci / K;
            int flat   = g_idx1[b * NC + ci];
            out[OFF_IND  + b * K + rank] = (float)flat;
            out[OFF_CLSO + b * K + rank] = (float)classe;
            out[OFF_YS   + b * K + rank] = (float)(flat >> 7);   // y = flat / 128
            out[OFF_XS   + b * K + rank] = (float)(flat & 127);  // x = flat % 128
        }
    }
}

// ---------------------------------------------------------------------------
extern "C" void kernel_launch(void* const* d_in, const int* in_sizes, int n_in,
                              void* d_out, int out_size)
{
    const float* hm = (const float*)d_in[0];
    float* out = (float*)d_out;
    stage1_kernel<<<BS * CLS, 256>>>(hm, out);
    stage2_kernel<<<BS, 256>>>(out, out);
}